// round 6
// baseline (speedup 1.0000x reference)
#include <cuda_runtime.h>
#include <cuda_fp16.h>
#include <cstdint>

#define N_USERS 100000
#define M_ITEMS 50000
#define N_NODES (N_USERS + M_ITEMS)        // 150000
#define N_EDGES 6000000
#define DIM 64
#define ROW_H2 (DIM / 2)                   // 32 half2 per node row
#define N_H2 ((size_t)N_NODES * ROW_H2)    // 4,800,000 half2

#define SCAN_B 1024
#define NB_SCAN ((N_NODES + SCAN_B - 1) / SCAN_B)   // 147

// ---- static scratch (no allocation allowed; zero-initialized at load) ------
__device__ __half2 g_b0[N_H2];       // 19.2 MB  h after 0 hops (quantized input)
__device__ __half2 g_b1[N_H2];       // 19.2 MB  h after 1 hop
__device__ __half2 g_b2[N_H2];       // 19.2 MB  h after 2 hops
__device__ int2    g_edges[N_EDGES]; // 48 MB    (src*32, val_bits) sorted by dst
__device__ int     g_cnt[N_NODES];   // INVARIANT: == 0 at kernel_launch entry
                                     // (zeroed by final spmm of previous run;
                                     //  zero-init on first run)
__device__ int     g_off[N_NODES];
__device__ int     g_pos[N_NODES];
__device__ int     g_part[NB_SCAN];

// ---------------------------------------------------------------------------
// Fused: b0 = fp16(concat(user_emb, item_emb))  AND  histogram of dst.
// Requires g_cnt == 0 at entry (see invariant above).
// ---------------------------------------------------------------------------
__global__ void init_hist_kernel(const float* __restrict__ user_emb,
                                 const float* __restrict__ item_emb,
                                 const int*   __restrict__ dst) {
    size_t i = (size_t)blockIdx.x * blockDim.x + threadIdx.x;
    if (i < N_H2) {
        size_t user2 = (size_t)N_USERS * ROW_H2;
        float2 v = (i < user2) ? ((const float2*)user_emb)[i]
                               : ((const float2*)item_emb)[i - user2];
        g_b0[i] = __floats2half2_rn(v.x, v.y);
    }
    if (i < N_EDGES) atomicAdd(&g_cnt[dst[i]], 1);
}

// ---------------------------------------------------------------------------
// CSR build
// ---------------------------------------------------------------------------
__global__ void block_reduce_kernel() {        // g_cnt -> g_part[b]
    __shared__ int sm[SCAN_B];
    int idx = blockIdx.x * SCAN_B + threadIdx.x;
    sm[threadIdx.x] = (idx < N_NODES) ? g_cnt[idx] : 0;
    __syncthreads();
    for (int s = SCAN_B / 2; s > 0; s >>= 1) {
        if (threadIdx.x < s) sm[threadIdx.x] += sm[threadIdx.x + s];
        __syncthreads();
    }
    if (threadIdx.x == 0) g_part[blockIdx.x] = sm[0];
}

// Exclusive scan of g_cnt -> g_off, g_pos. Block b's base computed inline
// as a warp-parallel sum over g_part[0..b-1] (<=147 ints).
__global__ void scan_final_kernel() {
    __shared__ int sm[SCAN_B];
    __shared__ int base_sh;
    int b = blockIdx.x;
    if (threadIdx.x < 32) {
        int acc = 0;
        for (int k = (int)threadIdx.x; k < b; k += 32) acc += g_part[k];
        #pragma unroll
        for (int o = 16; o > 0; o >>= 1) acc += __shfl_down_sync(0xffffffffu, acc, o);
        if (threadIdx.x == 0) base_sh = acc;
    }
    int idx = b * SCAN_B + threadIdx.x;
    int x = (idx < N_NODES) ? g_cnt[idx] : 0;
    sm[threadIdx.x] = x;
    __syncthreads();
    for (int o = 1; o < SCAN_B; o <<= 1) {     // inclusive Hillis-Steele
        int t = (threadIdx.x >= o) ? sm[threadIdx.x - o] : 0;
        __syncthreads();
        sm[threadIdx.x] += t;
        __syncthreads();
    }
    if (idx < N_NODES) {
        int excl = sm[threadIdx.x] - x + base_sh;
        g_off[idx] = excl;
        g_pos[idx] = excl;
    }
}

__global__ void scatter_kernel(const int* __restrict__ src,
                               const int* __restrict__ dst,
                               const float* __restrict__ val) {
    int e = blockIdx.x * blockDim.x + threadIdx.x;
    if (e < N_EDGES) {
        int p = atomicAdd(&g_pos[dst[e]], 1);
        // pre-bake src row offset in half2 units (src * 32)
        g_edges[p] = make_int2(src[e] * ROW_H2, __float_as_int(val[e]));
    }
}

// ---------------------------------------------------------------------------
// CSR SpMM: one warp per destination node, one half2 (2 dims) per lane.
// Edge batches of 32 staged through smem (LDS.64 broadcast, conflict-free).
// f32 accumulation in registers. FINAL fuses out = (b0+b1+b2+h3)*0.25 in f32
// and restores the g_cnt == 0 invariant for the next execution.
// ---------------------------------------------------------------------------
template<bool FINAL>
__global__ __launch_bounds__(256)
void spmm_csr_kernel(const __half2* __restrict__ hin,
                     __half2* __restrict__ hout,
                     float* __restrict__ out) {
    __shared__ int2 sm_ed[8][32];
    int wl   = threadIdx.x >> 5;
    int node = blockIdx.x * (blockDim.x >> 5) + wl;
    int lane = threadIdx.x & 31;
    if (node >= N_NODES) return;

    int start = g_off[node];
    int n     = g_cnt[node];

    float2 s = make_float2(0.f, 0.f);
    int i = 0;
    for (; i + 32 <= n; i += 32) {
        sm_ed[wl][lane] = __ldg(&g_edges[start + i + lane]);
        __syncwarp();
        #pragma unroll 8
        for (int j = 0; j < 32; j++) {
            int2 e = sm_ed[wl][j];
            float  v = __int_as_float(e.y);
            float2 x = __half22float2(__ldg(&hin[e.x + lane]));
            s.x += v * x.x;
            s.y += v * x.y;
        }
        __syncwarp();
    }
    int rem = n - i;
    if (rem > 0) {
        int2 ed = make_int2(0, 0);
        if (lane < rem) ed = __ldg(&g_edges[start + i + lane]);
        sm_ed[wl][lane] = ed;
        __syncwarp();
        for (int j = 0; j < rem; j++) {
            int2 e = sm_ed[wl][j];
            float  v = __int_as_float(e.y);
            float2 x = __half22float2(__ldg(&hin[e.x + lane]));
            s.x += v * x.x;
            s.y += v * x.y;
        }
    }

    size_t o = (size_t)node * ROW_H2 + lane;
    if (!FINAL) {
        hout[o] = __floats2half2_rn(s.x, s.y);
    } else {
        float2 a0 = __half22float2(g_b0[o]);
        float2 a1 = __half22float2(g_b1[o]);
        float2 a2 = __half22float2(hin[o]);   // hin == g_b2 in the final layer
        float2 r;
        r.x = (a0.x + a1.x + a2.x + s.x) * 0.25f;
        r.y = (a0.y + a1.y + a2.y + s.y) * 0.25f;
        ((float2*)out)[o] = r;
        if (lane == 0) g_cnt[node] = 0;       // restore invariant for next run
    }
}

// ---------------------------------------------------------------------------
extern "C" void kernel_launch(void* const* d_in, const int* in_sizes, int n_in,
                              void* d_out, int out_size) {
    const float* user_emb = (const float*)d_in[0];
    const float* item_emb = (const float*)d_in[1];
    const int*   edge_src = (const int*)d_in[2];
    const int*   edge_dst = (const int*)d_in[3];
    const float* edge_val = (const float*)d_in[4];
    float* out = (float*)d_out;

    __half2 *b0, *b1, *b2;
    cudaGetSymbolAddress((void**)&b0, g_b0);
    cudaGetSymbolAddress((void**)&b1, g_b1);
    cudaGetSymbolAddress((void**)&b2, g_b2);

    const int TB = 256;
    const int grid_edge = (N_EDGES + TB - 1) / TB;                 // covers N_H2 too
    const int grid_spmm = (N_NODES * 32 + TB - 1) / TB;            // 1 warp / node

    // 0: fused init + dst histogram (g_cnt is 0 on entry by invariant)
    init_hist_kernel<<<grid_edge, TB>>>(user_emb, item_emb, edge_dst);
    // 1-2: scan
    block_reduce_kernel<<<NB_SCAN, SCAN_B>>>();
    scan_final_kernel<<<NB_SCAN, SCAN_B>>>();
    // 3: counting-sort edges by dst
    scatter_kernel<<<grid_edge, TB>>>(edge_src, edge_dst, edge_val);

    // 4: Layer 1: b0 -> b1
    spmm_csr_kernel<false><<<grid_spmm, TB>>>(b0, b1, nullptr);
    // 5: Layer 2: b1 -> b2   (this is the ncu -s 5 profile slot)
    spmm_csr_kernel<false><<<grid_spmm, TB>>>(b1, b2, nullptr);
    // 6: Layer 3: b2 -> (h3 on the fly), out = (b0+b1+b2+h3) * 0.25, reset g_cnt
    spmm_csr_kernel<true><<<grid_spmm, TB>>>(b2, nullptr, out);
}